// round 2
// baseline (speedup 1.0000x reference)
#include <cuda_runtime.h>

// Scratch for per-row losses (allocation-free rule: __device__ global).
#define MAX_ROWS 16384
__device__ float g_row_loss[MAX_ROWS];

// Combine two (max, sumexp) partial logsumexp states.
__device__ __forceinline__ void lse_combine(float& m, float& s, float m2, float s2) {
    float mn = fmaxf(m, m2);
    s = s * __expf(m - mn) + s2 * __expf(m2 - mn);
    m = mn;
}

// One block per row: online logsumexp over C floats + gather target logit.
__global__ __launch_bounds__(256)
void row_lse_kernel(const float* __restrict__ logits,
                    const int* __restrict__ targets,   // int32: JAX demotes int64->int32
                    int C)
{
    const int row  = blockIdx.x;
    const float* rowp = logits + (size_t)row * (size_t)C;
    const float4* p4  = reinterpret_cast<const float4*>(rowp);
    const int n4 = C >> 2;

    // Running (max, sum of exp(x - max)) per thread.
    // -1e30f sentinel (not -inf) keeps exp(m - mn) well-defined (underflows to 0).
    float m = -1e30f;
    float s = 0.0f;

    // Main loop: vectorized, chunk-local max => 5 exps per 4 elements.
    for (int i = threadIdx.x; i < n4; i += blockDim.x) {
        float4 v = p4[i];
        float m4 = fmaxf(fmaxf(v.x, v.y), fmaxf(v.z, v.w));
        float mn = fmaxf(m, m4);
        s = s * __expf(m - mn)
          + __expf(v.x - mn) + __expf(v.y - mn)
          + __expf(v.z - mn) + __expf(v.w - mn);
        m = mn;
    }
    // Tail for C % 4 != 0 (not hit for C=32000, kept for generality).
    for (int i = (n4 << 2) + threadIdx.x; i < C; i += blockDim.x) {
        float x  = rowp[i];
        float mn = fmaxf(m, x);
        s = s * __expf(m - mn) + __expf(x - mn);
        m = mn;
    }

    // Intra-warp reduction of (m, s).
    #pragma unroll
    for (int off = 16; off > 0; off >>= 1) {
        float m2 = __shfl_down_sync(0xffffffffu, m, off);
        float s2 = __shfl_down_sync(0xffffffffu, s, off);
        lse_combine(m, s, m2, s2);
    }

    // Cross-warp reduction via shared memory (8 warps @ 256 threads).
    __shared__ float sm[8];
    __shared__ float ss[8];
    const int wid = threadIdx.x >> 5;
    const int lid = threadIdx.x & 31;
    if (lid == 0) { sm[wid] = m; ss[wid] = s; }
    __syncthreads();

    if (wid == 0) {
        const int nw = blockDim.x >> 5;
        m = (lid < nw) ? sm[lid] : -1e30f;
        s = (lid < nw) ? ss[lid] : 0.0f;
        #pragma unroll
        for (int off = 4; off > 0; off >>= 1) {
            float m2 = __shfl_down_sync(0xffffffffu, m, off);
            float s2 = __shfl_down_sync(0xffffffffu, s, off);
            lse_combine(m, s, m2, s2);
        }
        if (lid == 0) {
            int t = targets[row];
            // Clamp defensively: any dtype misinterpretation must not produce
            // an out-of-bounds gather (CE error is << rel_err tolerance anyway).
            t = min(max(t, 0), C - 1);
            float xt = __ldg(rowp + t);
            // per-row CE contribution: logsumexp(row) - logits[row, target]
            g_row_loss[row] = (m + __logf(s)) - xt;
        }
    }
}

// Reduce row losses -> mean, add the (input-independent) uniqueness penalty.
__global__ __launch_bounds__(1024)
void finalize_kernel(float* __restrict__ out, int B, float penalty)
{
    float acc = 0.0f;
    for (int i = threadIdx.x; i < B; i += blockDim.x)
        acc += g_row_loss[i];

    #pragma unroll
    for (int off = 16; off > 0; off >>= 1)
        acc += __shfl_down_sync(0xffffffffu, acc, off);

    __shared__ float sh[32];
    const int wid = threadIdx.x >> 5;
    const int lid = threadIdx.x & 31;
    if (lid == 0) sh[wid] = acc;
    __syncthreads();

    if (wid == 0) {
        const int nw = blockDim.x >> 5;
        acc = (lid < nw) ? sh[lid] : 0.0f;
        #pragma unroll
        for (int off = 16; off > 0; off >>= 1)
            acc += __shfl_down_sync(0xffffffffu, acc, off);
        if (lid == 0)
            out[0] = acc / (float)B + penalty;
    }
}

extern "C" void kernel_launch(void* const* d_in, const int* in_sizes, int n_in,
                              void* d_out, int out_size)
{
    const float* logits  = (const float*)d_in[0];
    const int*   targets = (const int*)d_in[1];

    const int B = in_sizes[1];
    const int C = in_sizes[0] / B;

    // targets.view(B, -1) has T = 1 column => uniq = 1 per row =>
    // repeated = (C - 1) per row => penalty = 10 * B * (C - 1).
    const float penalty = (float)(10.0 * (double)B * (double)((C > 1) ? (C - 1) : 0));

    row_lse_kernel<<<B, 256>>>(logits, targets, C);
    finalize_kernel<<<1, 1024>>>((float*)d_out, B, penalty);
}